// round 1
// baseline (speedup 1.0000x reference)
#include <cuda_runtime.h>
#include <math.h>

#define B_  2
#define T_  2048
#define C_  768
#define H_  12
#define D_  64
#define M_  (B_ * T_)      // 4096 rows
#define PAD 65

// Scratch (allocation-free): qkv activations and attention output
__device__ float g_qkv[(size_t)M_ * 3 * C_];   // [B,T,3C]  ~37.7 MB
__device__ float g_y[(size_t)M_ * C_];         // [B,T,C]   ~12.6 MB

// ---------------------------------------------------------------------------
// Generic tiled GEMM with fused bias: out[M,N] = A[M,K] @ W[K,N] + bias[N]
// 64x64 tile, BK=16, 256 threads, 4x4 accumulators per thread.
// Requires M%64==0, N%64==0, K%16==0 (true for all our shapes).
// ---------------------------------------------------------------------------
__global__ void gemm_bias_kernel(const float* __restrict__ A,
                                 const float* __restrict__ W,
                                 const float* __restrict__ bias,
                                 float* __restrict__ out,
                                 int K, int N) {
    __shared__ float As[64][17];
    __shared__ float Bs[16][65];
    const int tid = threadIdx.x;
    const int tx = tid & 15, ty = tid >> 4;
    const int rowBase = blockIdx.y * 64;
    const int colBase = blockIdx.x * 64;

    float acc[4][4] = {};

    for (int k0 = 0; k0 < K; k0 += 16) {
        // Load A tile 64x16
        #pragma unroll
        for (int t = 0; t < 4; t++) {
            int e = tid + 256 * t;
            int r = e >> 4, c = e & 15;
            As[r][c] = A[(size_t)(rowBase + r) * K + (k0 + c)];
        }
        // Load W tile 16x64 (coalesced rows of 64)
        #pragma unroll
        for (int t = 0; t < 4; t++) {
            int e = tid + 256 * t;
            int r = e >> 6, c = e & 63;
            Bs[r][c] = W[(size_t)(k0 + r) * N + (colBase + c)];
        }
        __syncthreads();

        #pragma unroll
        for (int kk = 0; kk < 16; kk++) {
            float a[4], bv[4];
            #pragma unroll
            for (int i = 0; i < 4; i++) a[i] = As[ty * 4 + i][kk];
            #pragma unroll
            for (int j = 0; j < 4; j++) bv[j] = Bs[kk][tx * 4 + j];
            #pragma unroll
            for (int i = 0; i < 4; i++)
                #pragma unroll
                for (int j = 0; j < 4; j++)
                    acc[i][j] += a[i] * bv[j];
        }
        __syncthreads();
    }

    #pragma unroll
    for (int i = 0; i < 4; i++) {
        int row = rowBase + ty * 4 + i;
        #pragma unroll
        for (int j = 0; j < 4; j++) {
            int col = colBase + tx * 4 + j;
            out[(size_t)row * N + col] = acc[i][j] + bias[col];
        }
    }
}

// ---------------------------------------------------------------------------
// Causal flash attention over qkv scratch.
// Grid: (T/64, B*H). 256 threads (16x16), each owns a 4x4 patch of the
// 64x64 S tile and a 4x4 patch of the 64x64 (rows x headdim) O tile.
// Online softmax: per-row m/l replicated across the 16 threads of a row
// group, kept consistent via butterfly shuffles within 16-lane groups.
// Dynamic smem: Qs,Ks,Vs,Ps each 64x65 floats = 66560 B.
// ---------------------------------------------------------------------------
extern __shared__ float smem_attn[];

__global__ void attn_kernel(const float* __restrict__ qkv, float* __restrict__ y) {
    float* Qs = smem_attn;
    float* Ks = Qs + 64 * PAD;
    float* Vs = Ks + 64 * PAD;
    float* Ps = Vs + 64 * PAD;

    const int qb = blockIdx.x;
    const int bh = blockIdx.y;
    const int b = bh / H_, h = bh % H_;
    const int tid = threadIdx.x;
    const int tx = tid & 15, ty = tid >> 4;
    const int r0 = ty * 4, c0 = tx * 4;

    const float scale = 0.125f;                     // 1/sqrt(64)
    const size_t rowStride = 3 * C_;
    const float* base = qkv + (size_t)b * T_ * rowStride + (size_t)h * D_;

    // Load Q tile (scaled)
    for (int e = tid; e < 64 * D_; e += 256) {
        int r = e >> 6, d = e & 63;
        Qs[r * PAD + d] = base[(size_t)(qb * 64 + r) * rowStride + d] * scale;
    }

    float acc[4][4] = {};
    float m_i[4], l_i[4];
    #pragma unroll
    for (int i = 0; i < 4; i++) { m_i[i] = -1e30f; l_i[i] = 0.0f; }

    for (int kb = 0; kb <= qb; kb++) {
        __syncthreads();   // previous P@V (and Q load on iter 0) done before overwrite
        for (int e = tid; e < 64 * D_; e += 256) {
            int r = e >> 6, d = e & 63;
            size_t g = (size_t)(kb * 64 + r) * rowStride + d;
            Ks[r * PAD + d] = base[C_ + g];
            Vs[r * PAD + d] = base[2 * C_ + g];
        }
        __syncthreads();

        // S = Q @ K^T  (thread patch 4x4)
        float s[4][4] = {};
        #pragma unroll 8
        for (int d = 0; d < D_; d++) {
            float a[4], bv[4];
            #pragma unroll
            for (int i = 0; i < 4; i++) a[i] = Qs[(r0 + i) * PAD + d];
            #pragma unroll
            for (int j = 0; j < 4; j++) bv[j] = Ks[(c0 + j) * PAD + d];
            #pragma unroll
            for (int i = 0; i < 4; i++)
                #pragma unroll
                for (int j = 0; j < 4; j++)
                    s[i][j] += a[i] * bv[j];
        }

        // Causal mask (only diagonal block needs it)
        if (kb == qb) {
            #pragma unroll
            for (int i = 0; i < 4; i++)
                #pragma unroll
                for (int j = 0; j < 4; j++)
                    if (c0 + j > r0 + i) s[i][j] = -1e30f;
        }

        // Online softmax per row; write P to smem
        #pragma unroll
        for (int i = 0; i < 4; i++) {
            float mloc = fmaxf(fmaxf(s[i][0], s[i][1]), fmaxf(s[i][2], s[i][3]));
            #pragma unroll
            for (int off = 8; off; off >>= 1)
                mloc = fmaxf(mloc, __shfl_xor_sync(0xffffffffu, mloc, off));
            float mnew  = fmaxf(m_i[i], mloc);
            float alpha = __expf(m_i[i] - mnew);
            float p[4], psum = 0.0f;
            #pragma unroll
            for (int j = 0; j < 4; j++) {
                p[j] = __expf(s[i][j] - mnew);
                psum += p[j];
            }
            #pragma unroll
            for (int off = 8; off; off >>= 1)
                psum += __shfl_xor_sync(0xffffffffu, psum, off);
            l_i[i] = l_i[i] * alpha + psum;
            m_i[i] = mnew;
            #pragma unroll
            for (int j = 0; j < 4; j++) acc[i][j] *= alpha;
            #pragma unroll
            for (int j = 0; j < 4; j++) Ps[(r0 + i) * PAD + c0 + j] = p[j];
        }
        __syncthreads();

        // O += P @ V
        #pragma unroll 8
        for (int k = 0; k < 64; k++) {
            float pv[4], vv[4];
            #pragma unroll
            for (int i = 0; i < 4; i++) pv[i] = Ps[(r0 + i) * PAD + k];
            #pragma unroll
            for (int j = 0; j < 4; j++) vv[j] = Vs[k * PAD + c0 + j];
            #pragma unroll
            for (int i = 0; i < 4; i++)
                #pragma unroll
                for (int j = 0; j < 4; j++)
                    acc[i][j] += pv[i] * vv[j];
        }
    }

    // Write y[b, t, h*D + c]
    #pragma unroll
    for (int i = 0; i < 4; i++) {
        float inv = 1.0f / l_i[i];
        int t = qb * 64 + r0 + i;
        #pragma unroll
        for (int j = 0; j < 4; j++) {
            y[((size_t)b * T_ + t) * C_ + h * D_ + c0 + j] = acc[i][j] * inv;
        }
    }
}

// ---------------------------------------------------------------------------
extern "C" void kernel_launch(void* const* d_in, const int* in_sizes, int n_in,
                              void* d_out, int out_size) {
    const float* x        = (const float*)d_in[0];
    const float* c_attn_w = (const float*)d_in[1];
    const float* c_attn_b = (const float*)d_in[2];
    const float* c_proj_w = (const float*)d_in[3];
    const float* c_proj_b = (const float*)d_in[4];
    float* out = (float*)d_out;

    float *qkv, *y;
    cudaGetSymbolAddress((void**)&qkv, g_qkv);
    cudaGetSymbolAddress((void**)&y, g_y);

    dim3 blk(256);

    // 1) QKV projection: [4096,768] @ [768,2304] + bias
    gemm_bias_kernel<<<dim3((3 * C_) / 64, M_ / 64), blk>>>(x, c_attn_w, c_attn_b, qkv, C_, 3 * C_);

    // 2) Causal flash attention
    size_t smem = (size_t)4 * 64 * PAD * sizeof(float);  // 66560 B
    cudaFuncSetAttribute(attn_kernel, cudaFuncAttributeMaxDynamicSharedMemorySize, (int)smem);
    attn_kernel<<<dim3(T_ / 64, B_ * H_), blk, smem>>>(qkv, y);

    // 3) Output projection: [4096,768] @ [768,768] + bias
    gemm_bias_kernel<<<dim3(C_ / 64, M_ / 64), blk>>>(y, c_proj_w, c_proj_b, out, C_, C_);
}

// round 2
// speedup vs baseline: 1.7189x; 1.7189x over previous
#include <cuda_runtime.h>
#include <math.h>

#define B_  2
#define T_  2048
#define C_  768
#define H_  12
#define D_  64
#define M_  (B_ * T_)      // 4096 rows
#define PAD 65

// Scratch (allocation-free)
__device__ float g_qkv[(size_t)M_ * 3 * C_];   // [B,T,3C]
__device__ float g_y[(size_t)M_ * C_];         // [B,T,C]

// ---------------------------------------------------------------------------
// TF32 helpers
// ---------------------------------------------------------------------------
__device__ __forceinline__ unsigned f2tf(float x) {
    unsigned u;
    asm("cvt.rna.tf32.f32 %0, %1;" : "=r"(u) : "f"(x));
    return u;
}

__device__ __forceinline__ void mma8(float* c, const unsigned* a, const unsigned* b) {
    asm volatile(
        "mma.sync.aligned.m16n8k8.row.col.f32.tf32.tf32.f32 "
        "{%0,%1,%2,%3}, {%4,%5,%6,%7}, {%8,%9}, {%0,%1,%2,%3};"
        : "+f"(c[0]), "+f"(c[1]), "+f"(c[2]), "+f"(c[3])
        : "r"(a[0]), "r"(a[1]), "r"(a[2]), "r"(a[3]),
          "r"(b[0]), "r"(b[1]));
}

// ---------------------------------------------------------------------------
// TF32 tensor-core GEMM with fused bias: out[M,N] = A[M,K] @ W[K,N] + bias
// CTA tile 128x128, BK=32, 256 threads = 8 warps (4 x 2),
// warp tile 32(M) x 64(N): mt=2, nt=8 m16n8k8 tiles. fp32 accumulate.
// Requires M%128==0, N%128==0, K%32==0 (true: M=4096, N in {2304,768}, K=768).
// ---------------------------------------------------------------------------
#define BM 128
#define BN 128
#define BK 32
#define ASTR 36    // floats per A smem row  (banks: 4g+t -> conflict-free)
#define BSTR 136   // floats per B smem row  (banks: 8t+g -> conflict-free)

__global__ void __launch_bounds__(256, 1)
gemm_mma(const float* __restrict__ A, const float* __restrict__ W,
         const float* __restrict__ bias, float* __restrict__ out,
         int K, int N) {
    __shared__ unsigned As[BM * ASTR];   // 18432 B
    __shared__ unsigned Bs[BK * BSTR];   // 17408 B

    const int tid  = threadIdx.x;
    const int lane = tid & 31;
    const int warp = tid >> 5;
    const int wm = warp >> 1;         // 0..3
    const int wn = warp & 1;          // 0..1
    const int g = lane >> 2;          // groupID 0..7
    const int t = lane & 3;           // thread-in-group 0..3
    const int rowBase = blockIdx.y * BM;
    const int colBase = blockIdx.x * BN;

    float acc[2][8][4];
    #pragma unroll
    for (int i = 0; i < 2; i++)
        #pragma unroll
        for (int j = 0; j < 8; j++)
            #pragma unroll
            for (int k = 0; k < 4; k++) acc[i][j][k] = 0.0f;

    float4 aReg[4], bReg[4];

    // ---- global load (chunk at k0) into registers ----
    auto loadRegs = [&](int k0) {
        #pragma unroll
        for (int it = 0; it < 4; it++) {
            int e = tid + 256 * it;
            int r = e >> 3, c4 = e & 7;       // A: 128 rows x 8 float4
            aReg[it] = *reinterpret_cast<const float4*>(
                A + (size_t)(rowBase + r) * K + (k0 + 4 * c4));
        }
        #pragma unroll
        for (int it = 0; it < 4; it++) {
            int e = tid + 256 * it;
            int rk = e >> 5, c4 = e & 31;     // B: 32 rows x 32 float4
            bReg[it] = *reinterpret_cast<const float4*>(
                W + (size_t)(k0 + rk) * N + (colBase + 4 * c4));
        }
    };

    // ---- convert to tf32 (round-to-nearest) and store to smem ----
    auto storeSmem = [&]() {
        #pragma unroll
        for (int it = 0; it < 4; it++) {
            int e = tid + 256 * it;
            int r = e >> 3, c4 = e & 7;
            uint4 v;
            v.x = f2tf(aReg[it].x); v.y = f2tf(aReg[it].y);
            v.z = f2tf(aReg[it].z); v.w = f2tf(aReg[it].w);
            *reinterpret_cast<uint4*>(&As[r * ASTR + 4 * c4]) = v;
        }
        #pragma unroll
        for (int it = 0; it < 4; it++) {
            int e = tid + 256 * it;
            int rk = e >> 5, c4 = e & 31;
            uint4 v;
            v.x = f2tf(bReg[it].x); v.y = f2tf(bReg[it].y);
            v.z = f2tf(bReg[it].z); v.w = f2tf(bReg[it].w);
            *reinterpret_cast<uint4*>(&Bs[rk * BSTR + 4 * c4]) = v;
        }
    };

    loadRegs(0);
    storeSmem();
    __syncthreads();

    const int nChunks = K / BK;
    for (int ci = 0; ci < nChunks; ci++) {
        if (ci + 1 < nChunks) loadRegs((ci + 1) * BK);   // prefetch overlaps compute

        #pragma unroll
        for (int ks = 0; ks < 4; ks++) {
            unsigned af[2][4], bf[8][2];
            #pragma unroll
            for (int mt = 0; mt < 2; mt++) {
                const unsigned* p = &As[(wm * 32 + mt * 16 + g) * ASTR + ks * 8 + t];
                af[mt][0] = p[0];
                af[mt][2] = p[4];
                af[mt][1] = p[8 * ASTR];
                af[mt][3] = p[8 * ASTR + 4];
            }
            #pragma unroll
            for (int nt = 0; nt < 8; nt++) {
                const unsigned* p = &Bs[(ks * 8 + t) * BSTR + wn * 64 + nt * 8 + g];
                bf[nt][0] = p[0];
                bf[nt][1] = p[4 * BSTR];
            }
            #pragma unroll
            for (int mt = 0; mt < 2; mt++)
                #pragma unroll
                for (int nt = 0; nt < 8; nt++)
                    mma8(acc[mt][nt], af[mt], bf[nt]);
        }
        __syncthreads();
        if (ci + 1 < nChunks) {
            storeSmem();
            __syncthreads();
        }
    }

    // ---- epilogue: add bias, store ----
    #pragma unroll
    for (int mt = 0; mt < 2; mt++) {
        int row0 = rowBase + wm * 32 + mt * 16 + g;
        #pragma unroll
        for (int nt = 0; nt < 8; nt++) {
            int col = colBase + wn * 64 + nt * 8 + 2 * t;
            float b0 = bias[col], b1 = bias[col + 1];
            float2 v0 = make_float2(acc[mt][nt][0] + b0, acc[mt][nt][1] + b1);
            float2 v1 = make_float2(acc[mt][nt][2] + b0, acc[mt][nt][3] + b1);
            *reinterpret_cast<float2*>(out + (size_t)row0 * N + col) = v0;
            *reinterpret_cast<float2*>(out + (size_t)(row0 + 8) * N + col) = v1;
        }
    }
}

// ---------------------------------------------------------------------------
// Causal flash attention (fp32 SIMT, unchanged from R1)
// ---------------------------------------------------------------------------
extern __shared__ float smem_attn[];

__global__ void attn_kernel(const float* __restrict__ qkv, float* __restrict__ y) {
    float* Qs = smem_attn;
    float* Ks = Qs + 64 * PAD;
    float* Vs = Ks + 64 * PAD;
    float* Ps = Vs + 64 * PAD;

    const int qb = blockIdx.x;
    const int bh = blockIdx.y;
    const int b = bh / H_, h = bh % H_;
    const int tid = threadIdx.x;
    const int tx = tid & 15, ty = tid >> 4;
    const int r0 = ty * 4, c0 = tx * 4;

    const float scale = 0.125f;
    const size_t rowStride = 3 * C_;
    const float* base = qkv + (size_t)b * T_ * rowStride + (size_t)h * D_;

    for (int e = tid; e < 64 * D_; e += 256) {
        int r = e >> 6, d = e & 63;
        Qs[r * PAD + d] = base[(size_t)(qb * 64 + r) * rowStride + d] * scale;
    }

    float acc[4][4] = {};
    float m_i[4], l_i[4];
    #pragma unroll
    for (int i = 0; i < 4; i++) { m_i[i] = -1e30f; l_i[i] = 0.0f; }

    for (int kb = 0; kb <= qb; kb++) {
        __syncthreads();
        for (int e = tid; e < 64 * D_; e += 256) {
            int r = e >> 6, d = e & 63;
            size_t gidx = (size_t)(kb * 64 + r) * rowStride + d;
            Ks[r * PAD + d] = base[C_ + gidx];
            Vs[r * PAD + d] = base[2 * C_ + gidx];
        }
        __syncthreads();

        float s[4][4] = {};
        #pragma unroll 8
        for (int d = 0; d < D_; d++) {
            float a[4], bv[4];
            #pragma unroll
            for (int i = 0; i < 4; i++) a[i] = Qs[(r0 + i) * PAD + d];
            #pragma unroll
            for (int j = 0; j < 4; j++) bv[j] = Ks[(c0 + j) * PAD + d];
            #pragma unroll
            for (int i = 0; i < 4; i++)
                #pragma unroll
                for (int j = 0; j < 4; j++)
                    s[i][j] += a[i] * bv[j];
        }

        if (kb == qb) {
            #pragma unroll
            for (int i = 0; i < 4; i++)
                #pragma unroll
                for (int j = 0; j < 4; j++)
                    if (c0 + j > r0 + i) s[i][j] = -1e30f;
        }

        #pragma unroll
        for (int i = 0; i < 4; i++) {
            float mloc = fmaxf(fmaxf(s[i][0], s[i][1]), fmaxf(s[i][2], s[i][3]));
            #pragma unroll
            for (int off = 8; off; off >>= 1)
                mloc = fmaxf(mloc, __shfl_xor_sync(0xffffffffu, mloc, off));
            float mnew  = fmaxf(m_i[i], mloc);
            float alpha = __expf(m_i[i] - mnew);
            float p[4], psum = 0.0f;
            #pragma unroll
            for (int j = 0; j < 4; j++) {
                p[j] = __expf(s[i][j] - mnew);
                psum += p[j];
            }
            #pragma unroll
            for (int off = 8; off; off >>= 1)
                psum += __shfl_xor_sync(0xffffffffu, psum, off);
            l_i[i] = l_i[i] * alpha + psum;
            m_i[i] = mnew;
            #pragma unroll
            for (int j = 0; j < 4; j++) acc[i][j] *= alpha;
            #pragma unroll
            for (int j = 0; j < 4; j++) Ps[(r0 + i) * PAD + c0 + j] = p[j];
        }
        __syncthreads();

        #pragma unroll 8
        for (int k = 0; k < 64; k++) {
            float pv[4], vv[4];
            #pragma unroll
            for (int i = 0; i < 4; i++) pv[i] = Ps[(r0 + i) * PAD + k];
            #pragma unroll
            for (int j = 0; j < 4; j++) vv[j] = Vs[k * PAD + c0 + j];
            #pragma unroll
            for (int i = 0; i < 4; i++)
                #pragma unroll
                for (int j = 0; j < 4; j++)
                    acc[i][j] += pv[i] * vv[j];
        }
    }

    #pragma unroll
    for (int i = 0; i < 4; i++) {
        float inv = 1.0f / l_i[i];
        int tt = qb * 64 + r0 + i;
        #pragma unroll
        for (int j = 0; j < 4; j++) {
            y[((size_t)b * T_ + tt) * C_ + h * D_ + c0 + j] = acc[i][j] * inv;
        }
    }
}

// ---------------------------------------------------------------------------
extern "C" void kernel_launch(void* const* d_in, const int* in_sizes, int n_in,
                              void* d_out, int out_size) {
    const float* x        = (const float*)d_in[0];
    const float* c_attn_w = (const float*)d_in[1];
    const float* c_attn_b = (const float*)d_in[2];
    const float* c_proj_w = (const float*)d_in[3];
    const float* c_proj_b = (const float*)d_in[4];
    float* out = (float*)d_out;

    float *qkv, *y;
    cudaGetSymbolAddress((void**)&qkv, g_qkv);
    cudaGetSymbolAddress((void**)&y, g_y);

    // 1) QKV projection: [4096,768] @ [768,2304] + bias   (tensor cores, tf32)
    gemm_mma<<<dim3((3 * C_) / BN, M_ / BM), 256>>>(x, c_attn_w, c_attn_b, qkv, C_, 3 * C_);

    // 2) Causal flash attention (fp32)
    size_t smem = (size_t)4 * 64 * PAD * sizeof(float);
    cudaFuncSetAttribute(attn_kernel, cudaFuncAttributeMaxDynamicSharedMemorySize, (int)smem);
    attn_kernel<<<dim3(T_ / 64, B_ * H_), 256, smem>>>(qkv, y);

    // 3) Output projection: [4096,768] @ [768,768] + bias (tensor cores, tf32)
    gemm_mma<<<dim3(C_ / BN, M_ / BM), 256>>>(y, c_proj_w, c_proj_b, out, C_, C_);
}

// round 3
// speedup vs baseline: 3.5378x; 2.0581x over previous
#include <cuda_runtime.h>
#include <math.h>

#define B_  2
#define T_  2048
#define C_  768
#define H_  12
#define D_  64
#define M_  (B_ * T_)      // 4096 rows

// Scratch (allocation-free)
__device__ float g_qkv[(size_t)M_ * 3 * C_];   // [B,T,3C]
__device__ float g_y[(size_t)M_ * C_];         // [B,T,C]

// ---------------------------------------------------------------------------
// TF32 helpers
// ---------------------------------------------------------------------------
__device__ __forceinline__ unsigned f2tf(float x) {
    unsigned u;
    asm("cvt.rna.tf32.f32 %0, %1;" : "=r"(u) : "f"(x));
    return u;
}

__device__ __forceinline__ void mma8(float* c, const unsigned* a, const unsigned* b) {
    asm volatile(
        "mma.sync.aligned.m16n8k8.row.col.f32.tf32.tf32.f32 "
        "{%0,%1,%2,%3}, {%4,%5,%6,%7}, {%8,%9}, {%0,%1,%2,%3};"
        : "+f"(c[0]), "+f"(c[1]), "+f"(c[2]), "+f"(c[3])
        : "r"(a[0]), "r"(a[1]), "r"(a[2]), "r"(a[3]),
          "r"(b[0]), "r"(b[1]));
}

// ---------------------------------------------------------------------------
// TF32 tensor-core GEMM with fused bias (unchanged from R2)
// ---------------------------------------------------------------------------
#define BM 128
#define BN 128
#define BK 32
#define ASTR 36
#define BSTR 136

__global__ void __launch_bounds__(256, 1)
gemm_mma(const float* __restrict__ A, const float* __restrict__ W,
         const float* __restrict__ bias, float* __restrict__ out,
         int K, int N) {
    __shared__ unsigned As[BM * ASTR];
    __shared__ unsigned Bs[BK * BSTR];

    const int tid  = threadIdx.x;
    const int lane = tid & 31;
    const int warp = tid >> 5;
    const int wm = warp >> 1;
    const int wn = warp & 1;
    const int g = lane >> 2;
    const int t = lane & 3;
    const int rowBase = blockIdx.y * BM;
    const int colBase = blockIdx.x * BN;

    float acc[2][8][4];
    #pragma unroll
    for (int i = 0; i < 2; i++)
        #pragma unroll
        for (int j = 0; j < 8; j++)
            #pragma unroll
            for (int k = 0; k < 4; k++) acc[i][j][k] = 0.0f;

    float4 aReg[4], bReg[4];

    auto loadRegs = [&](int k0) {
        #pragma unroll
        for (int it = 0; it < 4; it++) {
            int e = tid + 256 * it;
            int r = e >> 3, c4 = e & 7;
            aReg[it] = *reinterpret_cast<const float4*>(
                A + (size_t)(rowBase + r) * K + (k0 + 4 * c4));
        }
        #pragma unroll
        for (int it = 0; it < 4; it++) {
            int e = tid + 256 * it;
            int rk = e >> 5, c4 = e & 31;
            bReg[it] = *reinterpret_cast<const float4*>(
                W + (size_t)(k0 + rk) * N + (colBase + 4 * c4));
        }
    };

    auto storeSmem = [&]() {
        #pragma unroll
        for (int it = 0; it < 4; it++) {
            int e = tid + 256 * it;
            int r = e >> 3, c4 = e & 7;
            uint4 v;
            v.x = f2tf(aReg[it].x); v.y = f2tf(aReg[it].y);
            v.z = f2tf(aReg[it].z); v.w = f2tf(aReg[it].w);
            *reinterpret_cast<uint4*>(&As[r * ASTR + 4 * c4]) = v;
        }
        #pragma unroll
        for (int it = 0; it < 4; it++) {
            int e = tid + 256 * it;
            int rk = e >> 5, c4 = e & 31;
            uint4 v;
            v.x = f2tf(bReg[it].x); v.y = f2tf(bReg[it].y);
            v.z = f2tf(bReg[it].z); v.w = f2tf(bReg[it].w);
            *reinterpret_cast<uint4*>(&Bs[rk * BSTR + 4 * c4]) = v;
        }
    };

    loadRegs(0);
    storeSmem();
    __syncthreads();

    const int nChunks = K / BK;
    for (int ci = 0; ci < nChunks; ci++) {
        if (ci + 1 < nChunks) loadRegs((ci + 1) * BK);

        #pragma unroll
        for (int ks = 0; ks < 4; ks++) {
            unsigned af[2][4], bf[8][2];
            #pragma unroll
            for (int mt = 0; mt < 2; mt++) {
                const unsigned* p = &As[(wm * 32 + mt * 16 + g) * ASTR + ks * 8 + t];
                af[mt][0] = p[0];
                af[mt][2] = p[4];
                af[mt][1] = p[8 * ASTR];
                af[mt][3] = p[8 * ASTR + 4];
            }
            #pragma unroll
            for (int nt = 0; nt < 8; nt++) {
                const unsigned* p = &Bs[(ks * 8 + t) * BSTR + wn * 64 + nt * 8 + g];
                bf[nt][0] = p[0];
                bf[nt][1] = p[4 * BSTR];
            }
            #pragma unroll
            for (int mt = 0; mt < 2; mt++)
                #pragma unroll
                for (int nt = 0; nt < 8; nt++)
                    mma8(acc[mt][nt], af[mt], bf[nt]);
        }
        __syncthreads();
        if (ci + 1 < nChunks) {
            storeSmem();
            __syncthreads();
        }
    }

    #pragma unroll
    for (int mt = 0; mt < 2; mt++) {
        int row0 = rowBase + wm * 32 + mt * 16 + g;
        #pragma unroll
        for (int nt = 0; nt < 8; nt++) {
            int col = colBase + wn * 64 + nt * 8 + 2 * t;
            float b0 = bias[col], b1 = bias[col + 1];
            float2 v0 = make_float2(acc[mt][nt][0] + b0, acc[mt][nt][1] + b1);
            float2 v1 = make_float2(acc[mt][nt][2] + b0, acc[mt][nt][3] + b1);
            *reinterpret_cast<float2*>(out + (size_t)row0 * N + col) = v0;
            *reinterpret_cast<float2*>(out + (size_t)(row0 + 8) * N + col) = v1;
        }
    }
}

// ---------------------------------------------------------------------------
// TF32 tensor-core causal flash attention.
// Grid (T/128, B*H), 256 threads (8 warps). Each warp owns a 16-row query
// strip: full softmax rows stay inside one warp (quad shuffles only).
// Per 64-key block: S = Q@K^T (tf32 MMA), fp32 online softmax, P -> tf32
// via smem, O += P@V (tf32 MMA).
// ---------------------------------------------------------------------------
#define SQ 68   // Q smem stride  (4g+t banks -> conflict-free frag loads)
#define SK 68   // K smem stride
#define SV 72   // V smem stride  (8t+g banks -> conflict-free)
#define SP 68   // P smem stride

extern __shared__ unsigned sm_attn[];

__global__ void __launch_bounds__(256)
attn_mma(const float* __restrict__ qkv, float* __restrict__ y) {
    unsigned* Qs = sm_attn;                 // 128 x SQ
    unsigned* Ks = Qs + 128 * SQ;           // 64 x SK
    unsigned* Vs = Ks + 64 * SK;            // 64 x SV
    unsigned* Ps = Vs + 64 * SV;            // 128 x SP

    const int qb = (int)gridDim.x - 1 - (int)blockIdx.x;  // heavy tiles first
    const int bh = blockIdx.y;
    const int b = bh / H_, h = bh % H_;
    const int tid  = threadIdx.x;
    const int lane = tid & 31;
    const int warp = tid >> 5;
    const int g = lane >> 2;
    const int t = lane & 3;
    const int w16 = warp * 16;
    const int q0 = qb * 128;

    const size_t rowStride = 3 * C_;
    const float* base = qkv + (size_t)b * T_ * rowStride + (size_t)h * D_;
    const float scale = 0.125f;

    // Load Q tile (128 x 64), scale, convert to tf32.  2048 float4 loads.
    #pragma unroll
    for (int it = 0; it < 8; it++) {
        int e = tid + 256 * it;
        int r = e >> 4, c4 = e & 15;
        float4 v = *reinterpret_cast<const float4*>(
            base + (size_t)(q0 + r) * rowStride + 4 * c4);
        unsigned* dst = &Qs[r * SQ + 4 * c4];
        dst[0] = f2tf(v.x * scale); dst[1] = f2tf(v.y * scale);
        dst[2] = f2tf(v.z * scale); dst[3] = f2tf(v.w * scale);
    }

    float oAcc[8][4];
    #pragma unroll
    for (int i = 0; i < 8; i++)
        #pragma unroll
        for (int j = 0; j < 4; j++) oAcc[i][j] = 0.0f;
    float m_i[2] = {-1e30f, -1e30f};
    float l_i[2] = {0.0f, 0.0f};

    const int nkb = 2 * (qb + 1);
    for (int kb = 0; kb < nkb; kb++) {
        __syncthreads();   // previous block's K/V reads complete (covers Q load on iter 0)
        // Load K and V tiles (64 x 64 each), convert to tf32.
        #pragma unroll
        for (int it = 0; it < 4; it++) {
            int e = tid + 256 * it;
            int r = e >> 4, c4 = e & 15;
            size_t gofs = (size_t)(kb * 64 + r) * rowStride + 4 * c4;
            float4 kv = *reinterpret_cast<const float4*>(base + C_ + gofs);
            float4 vv = *reinterpret_cast<const float4*>(base + 2 * C_ + gofs);
            unsigned* kd = &Ks[r * SK + 4 * c4];
            kd[0] = f2tf(kv.x); kd[1] = f2tf(kv.y); kd[2] = f2tf(kv.z); kd[3] = f2tf(kv.w);
            unsigned* vd = &Vs[r * SV + 4 * c4];
            vd[0] = f2tf(vv.x); vd[1] = f2tf(vv.y); vd[2] = f2tf(vv.z); vd[3] = f2tf(vv.w);
        }
        __syncthreads();

        // ---- S = Q @ K^T  (16 x 64 strip per warp) ----
        float sA[8][4];
        #pragma unroll
        for (int i = 0; i < 8; i++)
            #pragma unroll
            for (int j = 0; j < 4; j++) sA[i][j] = 0.0f;

        #pragma unroll
        for (int kd = 0; kd < 8; kd++) {
            unsigned af[4], bf[8][2];
            const unsigned* qp = &Qs[(w16 + g) * SQ + kd * 8 + t];
            af[0] = qp[0];
            af[2] = qp[4];
            af[1] = qp[8 * SQ];
            af[3] = qp[8 * SQ + 4];
            #pragma unroll
            for (int nt = 0; nt < 8; nt++) {
                const unsigned* kp = &Ks[(nt * 8 + g) * SK + kd * 8 + t];
                bf[nt][0] = kp[0];
                bf[nt][1] = kp[4];
            }
            #pragma unroll
            for (int nt = 0; nt < 8; nt++)
                mma8(sA[nt], af, bf[nt]);
        }

        // ---- causal mask (only near-diagonal blocks) ----
        if (kb * 64 + 63 > q0 + w16) {
            int qr0 = q0 + w16 + g;
            int qr1 = qr0 + 8;
            #pragma unroll
            for (int nt = 0; nt < 8; nt++) {
                int kc0 = kb * 64 + nt * 8 + 2 * t;
                if (kc0 > qr0)     sA[nt][0] = -1e30f;
                if (kc0 + 1 > qr0) sA[nt][1] = -1e30f;
                if (kc0 > qr1)     sA[nt][2] = -1e30f;
                if (kc0 + 1 > qr1) sA[nt][3] = -1e30f;
            }
        }

        // ---- online softmax (rows g and g+8; reduce across quad t) ----
        float mx0 = -1e30f, mx1 = -1e30f;
        #pragma unroll
        for (int nt = 0; nt < 8; nt++) {
            mx0 = fmaxf(mx0, fmaxf(sA[nt][0], sA[nt][1]));
            mx1 = fmaxf(mx1, fmaxf(sA[nt][2], sA[nt][3]));
        }
        #pragma unroll
        for (int off = 1; off <= 2; off <<= 1) {
            mx0 = fmaxf(mx0, __shfl_xor_sync(0xffffffffu, mx0, off));
            mx1 = fmaxf(mx1, __shfl_xor_sync(0xffffffffu, mx1, off));
        }
        float mn0 = fmaxf(m_i[0], mx0);
        float mn1 = fmaxf(m_i[1], mx1);
        float al0 = __expf(m_i[0] - mn0);
        float al1 = __expf(m_i[1] - mn1);

        float ps0 = 0.0f, ps1 = 0.0f;
        #pragma unroll
        for (int nt = 0; nt < 8; nt++) {
            float p0 = __expf(sA[nt][0] - mn0);
            float p1 = __expf(sA[nt][1] - mn0);
            float p2 = __expf(sA[nt][2] - mn1);
            float p3 = __expf(sA[nt][3] - mn1);
            ps0 += p0 + p1;
            ps1 += p2 + p3;
            unsigned* pr0 = &Ps[(w16 + g) * SP + nt * 8 + 2 * t];
            pr0[0] = f2tf(p0); pr0[1] = f2tf(p1);
            unsigned* pr1 = &Ps[(w16 + g + 8) * SP + nt * 8 + 2 * t];
            pr1[0] = f2tf(p2); pr1[1] = f2tf(p3);
        }
        #pragma unroll
        for (int off = 1; off <= 2; off <<= 1) {
            ps0 += __shfl_xor_sync(0xffffffffu, ps0, off);
            ps1 += __shfl_xor_sync(0xffffffffu, ps1, off);
        }
        l_i[0] = l_i[0] * al0 + ps0;
        l_i[1] = l_i[1] * al1 + ps1;
        m_i[0] = mn0;
        m_i[1] = mn1;
        #pragma unroll
        for (int nt = 0; nt < 8; nt++) {
            oAcc[nt][0] *= al0; oAcc[nt][1] *= al0;
            oAcc[nt][2] *= al1; oAcc[nt][3] *= al1;
        }
        __syncwarp();

        // ---- O += P @ V ----
        #pragma unroll
        for (int kt = 0; kt < 8; kt++) {
            unsigned af[4], bf[8][2];
            const unsigned* pp = &Ps[(w16 + g) * SP + kt * 8 + t];
            af[0] = pp[0];
            af[2] = pp[4];
            af[1] = pp[8 * SP];
            af[3] = pp[8 * SP + 4];
            #pragma unroll
            for (int nt = 0; nt < 8; nt++) {
                const unsigned* vp = &Vs[(kt * 8 + t) * SV + nt * 8 + g];
                bf[nt][0] = vp[0];
                bf[nt][1] = vp[4 * SV];
            }
            #pragma unroll
            for (int nt = 0; nt < 8; nt++)
                mma8(oAcc[nt], af, bf[nt]);
        }
    }

    // ---- epilogue: normalize and store y[b, q, h*64 + d] ----
    float inv0 = 1.0f / l_i[0];
    float inv1 = 1.0f / l_i[1];
    int qr0 = q0 + w16 + g;
    float* yo = y + ((size_t)b * T_ + qr0) * C_ + h * D_;
    #pragma unroll
    for (int nt = 0; nt < 8; nt++) {
        int col = nt * 8 + 2 * t;
        *reinterpret_cast<float2*>(yo + col) =
            make_float2(oAcc[nt][0] * inv0, oAcc[nt][1] * inv0);
        *reinterpret_cast<float2*>(yo + (size_t)8 * C_ + col) =
            make_float2(oAcc[nt][2] * inv1, oAcc[nt][3] * inv1);
    }
}

// ---------------------------------------------------------------------------
extern "C" void kernel_launch(void* const* d_in, const int* in_sizes, int n_in,
                              void* d_out, int out_size) {
    const float* x        = (const float*)d_in[0];
    const float* c_attn_w = (const float*)d_in[1];
    const float* c_attn_b = (const float*)d_in[2];
    const float* c_proj_w = (const float*)d_in[3];
    const float* c_proj_b = (const float*)d_in[4];
    float* out = (float*)d_out;

    float *qkv, *y;
    cudaGetSymbolAddress((void**)&qkv, g_qkv);
    cudaGetSymbolAddress((void**)&y, g_y);

    // 1) QKV projection (tf32 tensor cores)
    gemm_mma<<<dim3((3 * C_) / BN, M_ / BM), 256>>>(x, c_attn_w, c_attn_b, qkv, C_, 3 * C_);

    // 2) Causal flash attention (tf32 tensor cores)
    size_t smem = (size_t)(128 * SQ + 64 * SK + 64 * SV + 128 * SP) * 4;  // 105472 B
    cudaFuncSetAttribute(attn_mma, cudaFuncAttributeMaxDynamicSharedMemorySize, (int)smem);
    attn_mma<<<dim3(T_ / 128, B_ * H_), 256, smem>>>(qkv, y);

    // 3) Output projection (tf32 tensor cores)
    gemm_mma<<<dim3(C_ / BN, M_ / BM), 256>>>(y, c_proj_w, c_proj_b, out, C_, C_);
}

// round 4
// speedup vs baseline: 3.7366x; 1.0562x over previous
#include <cuda_runtime.h>
#include <math.h>

#define B_  2
#define T_  2048
#define C_  768
#define H_  12
#define D_  64
#define M_  (B_ * T_)      // 4096 rows

// Scratch (allocation-free)
__device__ float g_qkv[(size_t)M_ * 3 * C_];   // [B,T,3C]
__device__ float g_y[(size_t)M_ * C_];         // [B,T,C]

extern __shared__ unsigned dynsmem[];

// ---------------------------------------------------------------------------
// TF32 helpers
// ---------------------------------------------------------------------------
__device__ __forceinline__ unsigned f2tf(float x) {
    unsigned u;
    asm("cvt.rna.tf32.f32 %0, %1;" : "=r"(u) : "f"(x));
    return u;
}

__device__ __forceinline__ void mma8(float* c, const unsigned* a, const unsigned* b) {
    asm volatile(
        "mma.sync.aligned.m16n8k8.row.col.f32.tf32.tf32.f32 "
        "{%0,%1,%2,%3}, {%4,%5,%6,%7}, {%8,%9}, {%0,%1,%2,%3};"
        : "+f"(c[0]), "+f"(c[1]), "+f"(c[2]), "+f"(c[3])
        : "r"(a[0]), "r"(a[1]), "r"(a[2]), "r"(a[3]),
          "r"(b[0]), "r"(b[1]));
}

// ---------------------------------------------------------------------------
// TF32 GEMM, double-buffered smem pipeline, one sync per k-chunk.
// CTA tile 128x128, BK=32, 256 threads, warp tile 32x64. fp32 accumulate.
// ---------------------------------------------------------------------------
#define BM 128
#define BN 128
#define BK 32
#define ASTR 36
#define BSTR 136
#define GSTAGE (BM * ASTR + BK * BSTR)   // words per pipeline stage

__global__ void __launch_bounds__(256, 1)
gemm_mma(const float* __restrict__ A, const float* __restrict__ W,
         const float* __restrict__ bias, float* __restrict__ out,
         int K, int N) {
    const int tid  = threadIdx.x;
    const int lane = tid & 31;
    const int warp = tid >> 5;
    const int wm = warp >> 1;
    const int wn = warp & 1;
    const int g = lane >> 2;
    const int t = lane & 3;
    const int rowBase = blockIdx.y * BM;
    const int colBase = blockIdx.x * BN;

    float acc[2][8][4];
    #pragma unroll
    for (int i = 0; i < 2; i++)
        #pragma unroll
        for (int j = 0; j < 8; j++)
            #pragma unroll
            for (int k = 0; k < 4; k++) acc[i][j][k] = 0.0f;

    float4 aReg[4], bReg[4];

    auto loadRegs = [&](int k0) {
        #pragma unroll
        for (int it = 0; it < 4; it++) {
            int e = tid + 256 * it;
            int r = e >> 3, c4 = e & 7;
            aReg[it] = *reinterpret_cast<const float4*>(
                A + (size_t)(rowBase + r) * K + (k0 + 4 * c4));
        }
        #pragma unroll
        for (int it = 0; it < 4; it++) {
            int e = tid + 256 * it;
            int rk = e >> 5, c4 = e & 31;
            bReg[it] = *reinterpret_cast<const float4*>(
                W + (size_t)(k0 + rk) * N + (colBase + 4 * c4));
        }
    };

    auto storeSmem = [&](int s) {
        unsigned* As = dynsmem + s * GSTAGE;
        unsigned* Bs = As + BM * ASTR;
        #pragma unroll
        for (int it = 0; it < 4; it++) {
            int e = tid + 256 * it;
            int r = e >> 3, c4 = e & 7;
            uint4 v;
            v.x = f2tf(aReg[it].x); v.y = f2tf(aReg[it].y);
            v.z = f2tf(aReg[it].z); v.w = f2tf(aReg[it].w);
            *reinterpret_cast<uint4*>(&As[r * ASTR + 4 * c4]) = v;
        }
        #pragma unroll
        for (int it = 0; it < 4; it++) {
            int e = tid + 256 * it;
            int rk = e >> 5, c4 = e & 31;
            uint4 v;
            v.x = f2tf(bReg[it].x); v.y = f2tf(bReg[it].y);
            v.z = f2tf(bReg[it].z); v.w = f2tf(bReg[it].w);
            *reinterpret_cast<uint4*>(&Bs[rk * BSTR + 4 * c4]) = v;
        }
    };

    const int nChunks = K / BK;
    loadRegs(0);
    storeSmem(0);
    if (nChunks > 1) loadRegs(BK);
    __syncthreads();

    for (int ci = 0; ci < nChunks; ci++) {
        const int cur = ci & 1;
        const unsigned* As = dynsmem + cur * GSTAGE;
        const unsigned* Bs = As + BM * ASTR;

        // compute chunk ci
        #pragma unroll
        for (int ks = 0; ks < 4; ks++) {
            unsigned af[2][4], bf[8][2];
            #pragma unroll
            for (int mt = 0; mt < 2; mt++) {
                const unsigned* p = &As[(wm * 32 + mt * 16 + g) * ASTR + ks * 8 + t];
                af[mt][0] = p[0];
                af[mt][2] = p[4];
                af[mt][1] = p[8 * ASTR];
                af[mt][3] = p[8 * ASTR + 4];
            }
            #pragma unroll
            for (int nt = 0; nt < 8; nt++) {
                const unsigned* p = &Bs[(ks * 8 + t) * BSTR + wn * 64 + nt * 8 + g];
                bf[nt][0] = p[0];
                bf[nt][1] = p[4 * BSTR];
            }
            #pragma unroll
            for (int mt = 0; mt < 2; mt++)
                #pragma unroll
                for (int nt = 0; nt < 8; nt++)
                    mma8(acc[mt][nt], af[mt], bf[nt]);
        }

        if (ci + 1 < nChunks) storeSmem((ci + 1) & 1);  // fill other buffer
        if (ci + 2 < nChunks) loadRegs((ci + 2) * BK);  // prefetch
        __syncthreads();
    }

    #pragma unroll
    for (int mt = 0; mt < 2; mt++) {
        int row0 = rowBase + wm * 32 + mt * 16 + g;
        #pragma unroll
        for (int nt = 0; nt < 8; nt++) {
            int col = colBase + wn * 64 + nt * 8 + 2 * t;
            float b0 = bias[col], b1 = bias[col + 1];
            float2 v0 = make_float2(acc[mt][nt][0] + b0, acc[mt][nt][1] + b1);
            float2 v1 = make_float2(acc[mt][nt][2] + b0, acc[mt][nt][3] + b1);
            *reinterpret_cast<float2*>(out + (size_t)row0 * N + col) = v0;
            *reinterpret_cast<float2*>(out + (size_t)(row0 + 8) * N + col) = v1;
        }
    }
}

// ---------------------------------------------------------------------------
// TF32 causal flash attention, double-buffered K/V pipeline.
// Grid (T/128, B*H), 8 warps; warp owns a 16-row query strip.
// ---------------------------------------------------------------------------
#define SQ 68
#define SK 68
#define SV 72
#define SP 68

__global__ void __launch_bounds__(256)
attn_mma(const float* __restrict__ qkv, float* __restrict__ y) {
    unsigned* Qs = dynsmem;                    // 128 x SQ
    unsigned* Ks = Qs + 128 * SQ;              // 2 x 64 x SK
    unsigned* Vs = Ks + 2 * 64 * SK;           // 2 x 64 x SV
    unsigned* Ps = Vs + 2 * 64 * SV;           // 128 x SP

    const int qb = (int)gridDim.x - 1 - (int)blockIdx.x;  // heavy tiles first
    const int bh = blockIdx.y;
    const int b = bh / H_, h = bh % H_;
    const int tid  = threadIdx.x;
    const int lane = tid & 31;
    const int warp = tid >> 5;
    const int g = lane >> 2;
    const int t = lane & 3;
    const int w16 = warp * 16;
    const int q0 = qb * 128;

    const size_t rowStride = 3 * C_;
    const float* base = qkv + (size_t)b * T_ * rowStride + (size_t)h * D_;
    const float scale = 0.125f;

    float4 kReg[4], vReg[4];

    auto ldKV = [&](int kb) {
        #pragma unroll
        for (int it = 0; it < 4; it++) {
            int e = tid + 256 * it;
            int r = e >> 4, c4 = e & 15;
            size_t gofs = (size_t)(kb * 64 + r) * rowStride + 4 * c4;
            kReg[it] = *reinterpret_cast<const float4*>(base + C_ + gofs);
            vReg[it] = *reinterpret_cast<const float4*>(base + 2 * C_ + gofs);
        }
    };
    auto stKV = [&](int s) {
        unsigned* Kss = Ks + s * 64 * SK;
        unsigned* Vss = Vs + s * 64 * SV;
        #pragma unroll
        for (int it = 0; it < 4; it++) {
            int e = tid + 256 * it;
            int r = e >> 4, c4 = e & 15;
            unsigned* kd = &Kss[r * SK + 4 * c4];
            kd[0] = f2tf(kReg[it].x); kd[1] = f2tf(kReg[it].y);
            kd[2] = f2tf(kReg[it].z); kd[3] = f2tf(kReg[it].w);
            unsigned* vd = &Vss[r * SV + 4 * c4];
            vd[0] = f2tf(vReg[it].x); vd[1] = f2tf(vReg[it].y);
            vd[2] = f2tf(vReg[it].z); vd[3] = f2tf(vReg[it].w);
        }
    };

    const int nkb = 2 * (qb + 1);

    // Prologue: stage 0 filled, stage-1 data in regs, Q tile loaded.
    ldKV(0);
    stKV(0);
    if (nkb > 1) ldKV(1);
    #pragma unroll
    for (int it = 0; it < 8; it++) {
        int e = tid + 256 * it;
        int r = e >> 4, c4 = e & 15;
        float4 v = *reinterpret_cast<const float4*>(
            base + (size_t)(q0 + r) * rowStride + 4 * c4);
        unsigned* dst = &Qs[r * SQ + 4 * c4];
        dst[0] = f2tf(v.x * scale); dst[1] = f2tf(v.y * scale);
        dst[2] = f2tf(v.z * scale); dst[3] = f2tf(v.w * scale);
    }
    __syncthreads();

    float oAcc[8][4];
    #pragma unroll
    for (int i = 0; i < 8; i++)
        #pragma unroll
        for (int j = 0; j < 4; j++) oAcc[i][j] = 0.0f;
    float m_i[2] = {-1e30f, -1e30f};
    float l_i[2] = {0.0f, 0.0f};

    for (int kb = 0; kb < nkb; kb++) {
        const int cur = kb & 1;
        const unsigned* Kss = Ks + cur * 64 * SK;
        const unsigned* Vss = Vs + cur * 64 * SV;

        // ---- S = Q @ K^T ----
        float sA[8][4];
        #pragma unroll
        for (int i = 0; i < 8; i++)
            #pragma unroll
            for (int j = 0; j < 4; j++) sA[i][j] = 0.0f;

        #pragma unroll
        for (int kd = 0; kd < 8; kd++) {
            unsigned af[4], bf[8][2];
            const unsigned* qp = &Qs[(w16 + g) * SQ + kd * 8 + t];
            af[0] = qp[0];
            af[2] = qp[4];
            af[1] = qp[8 * SQ];
            af[3] = qp[8 * SQ + 4];
            #pragma unroll
            for (int nt = 0; nt < 8; nt++) {
                const unsigned* kp = &Kss[(nt * 8 + g) * SK + kd * 8 + t];
                bf[nt][0] = kp[0];
                bf[nt][1] = kp[4];
            }
            #pragma unroll
            for (int nt = 0; nt < 8; nt++)
                mma8(sA[nt], af, bf[nt]);
        }

        // ---- causal mask ----
        if (kb * 64 + 63 > q0 + w16) {
            int qr0 = q0 + w16 + g;
            int qr1 = qr0 + 8;
            #pragma unroll
            for (int nt = 0; nt < 8; nt++) {
                int kc0 = kb * 64 + nt * 8 + 2 * t;
                if (kc0 > qr0)     sA[nt][0] = -1e30f;
                if (kc0 + 1 > qr0) sA[nt][1] = -1e30f;
                if (kc0 > qr1)     sA[nt][2] = -1e30f;
                if (kc0 + 1 > qr1) sA[nt][3] = -1e30f;
            }
        }

        // ---- online softmax ----
        float mx0 = -1e30f, mx1 = -1e30f;
        #pragma unroll
        for (int nt = 0; nt < 8; nt++) {
            mx0 = fmaxf(mx0, fmaxf(sA[nt][0], sA[nt][1]));
            mx1 = fmaxf(mx1, fmaxf(sA[nt][2], sA[nt][3]));
        }
        #pragma unroll
        for (int off = 1; off <= 2; off <<= 1) {
            mx0 = fmaxf(mx0, __shfl_xor_sync(0xffffffffu, mx0, off));
            mx1 = fmaxf(mx1, __shfl_xor_sync(0xffffffffu, mx1, off));
        }
        float mn0 = fmaxf(m_i[0], mx0);
        float mn1 = fmaxf(m_i[1], mx1);
        float al0 = __expf(m_i[0] - mn0);
        float al1 = __expf(m_i[1] - mn1);

        float ps0 = 0.0f, ps1 = 0.0f;
        #pragma unroll
        for (int nt = 0; nt < 8; nt++) {
            float p0 = __expf(sA[nt][0] - mn0);
            float p1 = __expf(sA[nt][1] - mn0);
            float p2 = __expf(sA[nt][2] - mn1);
            float p3 = __expf(sA[nt][3] - mn1);
            ps0 += p0 + p1;
            ps1 += p2 + p3;
            unsigned* pr0 = &Ps[(w16 + g) * SP + nt * 8 + 2 * t];
            pr0[0] = f2tf(p0); pr0[1] = f2tf(p1);
            unsigned* pr1 = &Ps[(w16 + g + 8) * SP + nt * 8 + 2 * t];
            pr1[0] = f2tf(p2); pr1[1] = f2tf(p3);
        }
        #pragma unroll
        for (int off = 1; off <= 2; off <<= 1) {
            ps0 += __shfl_xor_sync(0xffffffffu, ps0, off);
            ps1 += __shfl_xor_sync(0xffffffffu, ps1, off);
        }
        l_i[0] = l_i[0] * al0 + ps0;
        l_i[1] = l_i[1] * al1 + ps1;
        m_i[0] = mn0;
        m_i[1] = mn1;
        #pragma unroll
        for (int nt = 0; nt < 8; nt++) {
            oAcc[nt][0] *= al0; oAcc[nt][1] *= al0;
            oAcc[nt][2] *= al1; oAcc[nt][3] *= al1;
        }
        __syncwarp();

        // ---- O += P @ V ----
        #pragma unroll
        for (int kt = 0; kt < 8; kt++) {
            unsigned af[4], bf[8][2];
            const unsigned* pp = &Ps[(w16 + g) * SP + kt * 8 + t];
            af[0] = pp[0];
            af[2] = pp[4];
            af[1] = pp[8 * SP];
            af[3] = pp[8 * SP + 4];
            #pragma unroll
            for (int nt = 0; nt < 8; nt++) {
                const unsigned* vp = &Vss[(kt * 8 + t) * SV + nt * 8 + g];
                bf[nt][0] = vp[0];
                bf[nt][1] = vp[4 * SV];
            }
            #pragma unroll
            for (int nt = 0; nt < 8; nt++)
                mma8(oAcc[nt], af, bf[nt]);
        }

        if (kb + 1 < nkb) stKV((kb + 1) & 1);
        if (kb + 2 < nkb) ldKV(kb + 2);
        __syncthreads();
    }

    // ---- epilogue ----
    float inv0 = 1.0f / l_i[0];
    float inv1 = 1.0f / l_i[1];
    int qr0 = q0 + w16 + g;
    float* yo = y + ((size_t)b * T_ + qr0) * C_ + h * D_;
    #pragma unroll
    for (int nt = 0; nt < 8; nt++) {
        int col = nt * 8 + 2 * t;
        *reinterpret_cast<float2*>(yo + col) =
            make_float2(oAcc[nt][0] * inv0, oAcc[nt][1] * inv0);
        *reinterpret_cast<float2*>(yo + (size_t)8 * C_ + col) =
            make_float2(oAcc[nt][2] * inv1, oAcc[nt][3] * inv1);
    }
}

// ---------------------------------------------------------------------------
extern "C" void kernel_launch(void* const* d_in, const int* in_sizes, int n_in,
                              void* d_out, int out_size) {
    const float* x        = (const float*)d_in[0];
    const float* c_attn_w = (const float*)d_in[1];
    const float* c_attn_b = (const float*)d_in[2];
    const float* c_proj_w = (const float*)d_in[3];
    const float* c_proj_b = (const float*)d_in[4];
    float* out = (float*)d_out;

    float *qkv, *y;
    cudaGetSymbolAddress((void**)&qkv, g_qkv);
    cudaGetSymbolAddress((void**)&y, g_y);

    size_t gemmSmem = (size_t)2 * GSTAGE * 4;   // 71680 B
    cudaFuncSetAttribute(gemm_mma, cudaFuncAttributeMaxDynamicSharedMemorySize, (int)gemmSmem);

    size_t attnSmem = (size_t)(128 * SQ + 2 * 64 * SK + 2 * 64 * SV + 128 * SP) * 4;  // 141312 B
    cudaFuncSetAttribute(attn_mma, cudaFuncAttributeMaxDynamicSharedMemorySize, (int)attnSmem);

    // 1) QKV projection
    gemm_mma<<<dim3((3 * C_) / BN, M_ / BM), 256, gemmSmem>>>(x, c_attn_w, c_attn_b, qkv, C_, 3 * C_);

    // 2) Causal flash attention
    attn_mma<<<dim3(T_ / 128, B_ * H_), 256, attnSmem>>>(qkv, y);

    // 3) Output projection
    gemm_mma<<<dim3(C_ / BN, M_ / BM), 256, gemmSmem>>>(y, c_proj_w, c_proj_b, out, C_, C_);
}

// round 7
// speedup vs baseline: 7.9254x; 2.1210x over previous
#include <cuda_runtime.h>
#include <cuda_fp16.h>
#include <cstdint>

#define B_  2
#define T_  2048
#define C_  768
#define H_  12
#define D_  64
#define M_  (B_ * T_)      // 4096 rows

// Scratch (allocation-free), all fp16
__device__ __half g_xh[(size_t)M_ * C_];
__device__ __half g_wqkv[(size_t)C_ * 3 * C_];
__device__ __half g_wproj[(size_t)C_ * C_];
__device__ __half g_qkvh[(size_t)M_ * 3 * C_];
__device__ __half g_yh[(size_t)M_ * C_];

extern __shared__ char dynsmem[];

// ---------------------------------------------------------------------------
// PTX helpers
// ---------------------------------------------------------------------------
__device__ __forceinline__ uint32_t smem_u32(const void* p) {
    uint32_t a;
    asm("{ .reg .u64 t; cvta.to.shared.u64 t, %1; cvt.u32.u64 %0, t; }"
        : "=r"(a) : "l"(p));
    return a;
}

__device__ __forceinline__ void cpa16(uint32_t dst, const void* src) {
    asm volatile("cp.async.cg.shared.global [%0], [%1], 16;" :: "r"(dst), "l"(src));
}
#define CP_COMMIT() asm volatile("cp.async.commit_group;" ::: "memory")
#define CP_WAIT0()  asm volatile("cp.async.wait_group 0;" ::: "memory")
#define CP_WAIT1()  asm volatile("cp.async.wait_group 1;" ::: "memory")

__device__ __forceinline__ void ldsm4(unsigned* r, uint32_t a) {
    asm volatile("ldmatrix.sync.aligned.m8n8.x4.shared.b16 {%0,%1,%2,%3}, [%4];"
        : "=r"(r[0]), "=r"(r[1]), "=r"(r[2]), "=r"(r[3]) : "r"(a));
}
__device__ __forceinline__ void ldsm4t(unsigned* r, uint32_t a) {
    asm volatile("ldmatrix.sync.aligned.m8n8.x4.trans.shared.b16 {%0,%1,%2,%3}, [%4];"
        : "=r"(r[0]), "=r"(r[1]), "=r"(r[2]), "=r"(r[3]) : "r"(a));
}

__device__ __forceinline__ void mma16(float* c, const unsigned* a, const unsigned* b) {
    asm volatile(
        "mma.sync.aligned.m16n8k16.row.col.f32.f16.f16.f32 "
        "{%0,%1,%2,%3}, {%4,%5,%6,%7}, {%8,%9}, {%0,%1,%2,%3};"
        : "+f"(c[0]), "+f"(c[1]), "+f"(c[2]), "+f"(c[3])
        : "r"(a[0]), "r"(a[1]), "r"(a[2]), "r"(a[3]), "r"(b[0]), "r"(b[1]));
}

// ---------------------------------------------------------------------------
// fp32 -> fp16 conversion (one-time, pre-pass)
// ---------------------------------------------------------------------------
__global__ void f2h_kernel(const float* __restrict__ s, __half* __restrict__ d, int n4) {
    int i = blockIdx.x * blockDim.x + threadIdx.x;
    if (i < n4) {
        float4 v = reinterpret_cast<const float4*>(s)[i];
        __half2* o = reinterpret_cast<__half2*>(d) + 2 * i;
        o[0] = __floats2half2_rn(v.x, v.y);
        o[1] = __floats2half2_rn(v.z, v.w);
    }
}

// ---------------------------------------------------------------------------
// fp16 GEMM, cp.async 3-stage pipeline + ldmatrix + m16n8k16.
// CTA 128x128, BK=64, 256 threads, warp tile 32x64. fp32 accumulate.
// A [M,K] half row-major; W [K,N] half row-major; bias fp32; out half or fp32.
// ---------------------------------------------------------------------------
#define SAH 72                         // A smem row stride (halves)
#define SBH 136                        // B smem row stride (halves)
#define ASZ (128 * SAH * 2)            // 18432 B
#define STG_B (ASZ + 64 * SBH * 2)     // 35840 B per stage

template<int OUT_HALF>
__global__ void __launch_bounds__(256, 2)
gemm_h(const __half* __restrict__ A, const __half* __restrict__ W,
       const float* __restrict__ bias, void* __restrict__ outv, int K, int N) {
    const int tid = threadIdx.x, lane = tid & 31, warp = tid >> 5;
    const int wm = warp >> 1, wn = warp & 1, g = lane >> 2, t = lane & 3;
    const int rowBase = blockIdx.y * 128, colBase = blockIdx.x * 128;
    const uint32_t sb = smem_u32(dynsmem);

    auto fill = [&](int s, int k0) {
        uint32_t st = sb + s * STG_B;
        #pragma unroll
        for (int it = 0; it < 4; it++) {                 // A: 128 x 64 halves
            int e = tid + 256 * it, r = e >> 3, c = e & 7;
            cpa16(st + (r * SAH + c * 8) * 2, A + (size_t)(rowBase + r) * K + k0 + c * 8);
        }
        #pragma unroll
        for (int it = 0; it < 4; it++) {                 // B: 64 x 128 halves
            int e = tid + 256 * it, r = e >> 4, c = e & 15;
            cpa16(st + ASZ + (r * SBH + c * 8) * 2, W + (size_t)(k0 + r) * N + colBase + c * 8);
        }
    };

    float acc[2][8][4] = {};

    const int nCh = K / 64;   // 12
    fill(0, 0);  CP_COMMIT();
    fill(1, 64); CP_COMMIT();

    for (int c = 0; c < nCh; c++) {
        if (c + 1 < nCh) CP_WAIT1(); else CP_WAIT0();
        __syncthreads();
        if (c + 2 < nCh) { fill((c + 2) % 3, (c + 2) * 64); CP_COMMIT(); }

        uint32_t st = sb + (c % 3) * STG_B;
        #pragma unroll
        for (int ks = 0; ks < 4; ks++) {
            unsigned af[2][4], bf[8][2];
            #pragma unroll
            for (int mt = 0; mt < 2; mt++) {
                int row = wm * 32 + mt * 16 + (lane & 15);
                ldsm4(af[mt], st + row * (SAH * 2) + ks * 32 + ((lane & 16) ? 16 : 0));
            }
            #pragma unroll
            for (int np = 0; np < 4; np++) {
                int row = ks * 16 + (lane & 15);
                int col = wn * 64 + np * 16 + ((lane & 16) ? 8 : 0);
                unsigned r4[4];
                ldsm4t(r4, st + ASZ + row * (SBH * 2) + col * 2);
                bf[2 * np][0] = r4[0]; bf[2 * np][1] = r4[1];
                bf[2 * np + 1][0] = r4[2]; bf[2 * np + 1][1] = r4[3];
            }
            #pragma unroll
            for (int mt = 0; mt < 2; mt++)
                #pragma unroll
                for (int nt = 0; nt < 8; nt++)
                    mma16(acc[mt][nt], af[mt], bf[nt]);
        }
    }

    #pragma unroll
    for (int mt = 0; mt < 2; mt++) {
        int row0 = rowBase + wm * 32 + mt * 16 + g;
        #pragma unroll
        for (int nt = 0; nt < 8; nt++) {
            int col = colBase + wn * 64 + nt * 8 + 2 * t;
            float b0 = bias[col], b1 = bias[col + 1];
            if (OUT_HALF) {
                __half* out = (__half*)outv;
                *reinterpret_cast<__half2*>(out + (size_t)row0 * N + col) =
                    __floats2half2_rn(acc[mt][nt][0] + b0, acc[mt][nt][1] + b1);
                *reinterpret_cast<__half2*>(out + (size_t)(row0 + 8) * N + col) =
                    __floats2half2_rn(acc[mt][nt][2] + b0, acc[mt][nt][3] + b1);
            } else {
                float* out = (float*)outv;
                *reinterpret_cast<float2*>(out + (size_t)row0 * N + col) =
                    make_float2(acc[mt][nt][0] + b0, acc[mt][nt][1] + b1);
                *reinterpret_cast<float2*>(out + (size_t)(row0 + 8) * N + col) =
                    make_float2(acc[mt][nt][2] + b0, acc[mt][nt][3] + b1);
            }
        }
    }
}

// ---------------------------------------------------------------------------
// fp16 causal flash attention: cp.async 3-stage K/V pipeline, ldmatrix frags,
// m16n8k16 MMA, P kept in registers (C-layout == A-layout). Q frags loaded once.
// Grid (T/128, B*H), 8 warps; warp owns a 16-row query strip.
// ---------------------------------------------------------------------------
#define SH    72                     // Q/K/V smem row stride (halves)
#define QSZ   (128 * SH * 2)         // 18432 B
#define KVSZ  (64 * SH * 2)          // 9216 B
#define KVSTG (2 * KVSZ)             // K + V per stage

__global__ void __launch_bounds__(256, 2)
attn_h(const __half* __restrict__ qkv, __half* __restrict__ y) {
    const int qb = (int)gridDim.x - 1 - (int)blockIdx.x;   // heavy tiles first
    const int bh = blockIdx.y, b = bh / H_, h = bh % H_;
    const int tid = threadIdx.x, lane = tid & 31, warp = tid >> 5;
    const int g = lane >> 2, t = lane & 3, w16 = warp * 16, q0 = qb * 128;
    const size_t rs = 3 * C_;
    const __half* base = qkv + (size_t)b * T_ * rs + h * D_;
    const uint32_t sb = smem_u32(dynsmem);
    const uint32_t sQ = sb, sKV = sb + QSZ;

    auto fillKV = [&](int s, int kb) {
        uint32_t st = sKV + s * KVSTG;
        #pragma unroll
        for (int it = 0; it < 4; it++) {
            int e = tid + 256 * it;          // 1024 segs: 512 K + 512 V
            int hv = e >> 9;                 // 0: K, 1: V
            int r = (e >> 3) & 63, c = e & 7;
            cpa16(st + hv * KVSZ + (r * SH + c * 8) * 2,
                  base + (1 + hv) * C_ + (size_t)(kb * 64 + r) * rs + c * 8);
        }
    };

    // Prologue: Q + KV(0) in group 0, KV(1) in group 1.
    #pragma unroll
    for (int it = 0; it < 4; it++) {
        int e = tid + 256 * it, r = e >> 3, c = e & 7;
        cpa16(sQ + (r * SH + c * 8) * 2, base + (size_t)(q0 + r) * rs + c * 8);
    }
    const int nkb = 2 * (qb + 1);
    fillKV(0, 0); CP_COMMIT();
    if (nkb > 1) { fillKV(1, 1); CP_COMMIT(); }

    if (nkb > 1) CP_WAIT1(); else CP_WAIT0();
    __syncthreads();

    // Q fragments, loaded once
    unsigned qf[4][4];
    #pragma unroll
    for (int ks = 0; ks < 4; ks++) {
        int row = w16 + (lane & 15);
        ldsm4(qf[ks], sQ + row * (SH * 2) + ks * 32 + ((lane & 16) ? 16 : 0));
    }

    float oAcc[8][4] = {};
    float m_i[2] = {-1e30f, -1e30f}, l_i[2] = {0.0f, 0.0f};

    for (int kb = 0; kb < nkb; kb++) {
        if (kb + 1 < nkb) CP_WAIT1(); else CP_WAIT0();
        __syncthreads();
        if (kb + 2 < nkb) { fillKV((kb + 2) % 3, kb + 2); CP_COMMIT(); }

        const uint32_t sK = sKV + (kb % 3) * KVSTG;
        const uint32_t sV = sK + KVSZ;

        // ---- S = Q @ K^T ----
        float sA[8][4] = {};
        #pragma unroll
        for (int ks = 0; ks < 4; ks++) {
            unsigned bf[8][2];
            #pragma unroll
            for (int np = 0; np < 4; np++) {
                int row = np * 16 + ((lane & 16) ? 8 : 0) + (lane & 7);
                unsigned r4[4];
                ldsm4(r4, sK + row * (SH * 2) + ks * 32 + ((lane & 8) ? 16 : 0));
                bf[2 * np][0] = r4[0]; bf[2 * np][1] = r4[1];
                bf[2 * np + 1][0] = r4[2]; bf[2 * np + 1][1] = r4[3];
            }
            #pragma unroll
            for (int nt = 0; nt < 8; nt++)
                mma16(sA[nt], qf[ks], bf[nt]);
        }

        // scale
        #pragma unroll
        for (int nt = 0; nt < 8; nt++)
            #pragma unroll
            for (int j = 0; j < 4; j++) sA[nt][j] *= 0.125f;

        // causal mask (near-diagonal blocks only)
        if (kb * 64 + 63 > q0 + w16) {
            int qr0 = q0 + w16 + g, qr1 = qr0 + 8;
            #pragma unroll
            for (int nt = 0; nt < 8; nt++) {
                int kc = kb * 64 + nt * 8 + 2 * t;
                if (kc     > qr0) sA[nt][0] = -1e30f;
                if (kc + 1 > qr0) sA[nt][1] = -1e30f;
                if (kc     > qr1) sA[nt][2] = -1e30f;
                if (kc + 1 > qr1) sA[nt][3] = -1e30f;
            }
        }

        // ---- online softmax (rows g, g+8; quad reduce) ----
        float mx0 = -1e30f, mx1 = -1e30f;
        #pragma unroll
        for (int nt = 0; nt < 8; nt++) {
            mx0 = fmaxf(mx0, fmaxf(sA[nt][0], sA[nt][1]));
            mx1 = fmaxf(mx1, fmaxf(sA[nt][2], sA[nt][3]));
        }
        #pragma unroll
        for (int off = 1; off <= 2; off <<= 1) {
            mx0 = fmaxf(mx0, __shfl_xor_sync(0xffffffffu, mx0, off));
            mx1 = fmaxf(mx1, __shfl_xor_sync(0xffffffffu, mx1, off));
        }
        float mn0 = fmaxf(m_i[0], mx0), mn1 = fmaxf(m_i[1], mx1);
        float al0 = __expf(m_i[0] - mn0), al1 = __expf(m_i[1] - mn1);

        unsigned pf[4][4];
        float ps0 = 0.0f, ps1 = 0.0f;
        #pragma unroll
        for (int nt = 0; nt < 8; nt++) {
            float p0 = __expf(sA[nt][0] - mn0), p1 = __expf(sA[nt][1] - mn0);
            float p2 = __expf(sA[nt][2] - mn1), p3 = __expf(sA[nt][3] - mn1);
            ps0 += p0 + p1; ps1 += p2 + p3;
            __half2 hA = __floats2half2_rn(p0, p1);
            __half2 hB = __floats2half2_rn(p2, p3);
            pf[nt >> 1][(nt & 1) * 2 + 0] = *reinterpret_cast<unsigned*>(&hA);
            pf[nt >> 1][(nt & 1) * 2 + 1] = *reinterpret_cast<unsigned*>(&hB);
        }
        #pragma unroll
        for (int off = 1; off <= 2; off <<= 1) {
            ps0 += __shfl_xor_sync(0xffffffffu, ps0, off);
            ps1 += __shfl_xor_sync(0xffffffffu, ps1, off);
        }
        l_i[0] = l_i[0] * al0 + ps0;
        l_i[1] = l_i[1] * al1 + ps1;
        m_i[0] = mn0; m_i[1] = mn1;
        #pragma unroll
        for (int nt = 0; nt < 8; nt++) {
            oAcc[nt][0] *= al0; oAcc[nt][1] *= al0;
            oAcc[nt][2] *= al1; oAcc[nt][3] *= al1;
        }

        // ---- O += P @ V  (P fragments straight from registers) ----
        #pragma unroll
        for (int kt = 0; kt < 4; kt++) {
            unsigned vf[8][2];
            #pragma unroll
            for (int np = 0; np < 4; np++) {
                int row = kt * 16 + (lane & 15);
                unsigned r4[4];
                ldsm4t(r4, sV + row * (SH * 2) + np * 32 + ((lane & 16) ? 16 : 0));
                vf[2 * np][0] = r4[0]; vf[2 * np][1] = r4[1];
                vf[2 * np + 1][0] = r4[2]; vf[2 * np + 1][1] = r4[3];
            }
            #pragma unroll
            for (int nt = 0; nt < 8; nt++)
                mma16(oAcc[nt], pf[kt], vf[nt]);
        }
    }

    // ---- epilogue: normalize, store y (half) ----
    float inv0 = 1.0f / l_i[0], inv1 = 1.0f / l_i[1];
    int qr = q0 + w16 + g;
    __half* yo = y + ((size_t)b * T_ + qr) * C_ + h * D_;
    #pragma unroll
    for (int nt = 0; nt < 8; nt++) {
        int col = nt * 8 + 2 * t;
        *reinterpret_cast<__half2*>(yo + col) =
            __floats2half2_rn(oAcc[nt][0] * inv0, oAcc[nt][1] * inv0);
        *reinterpret_cast<__half2*>(yo + (size_t)8 * C_ + col) =
            __floats2half2_rn(oAcc[nt][2] * inv1, oAcc[nt][3] * inv1);
    }
}

// ---------------------------------------------------------------------------
extern "C" void kernel_launch(void* const* d_in, const int* in_sizes, int n_in,
                              void* d_out, int out_size) {
    const float* x        = (const float*)d_in[0];
    const float* c_attn_w = (const float*)d_in[1];
    const float* c_attn_b = (const float*)d_in[2];
    const float* c_proj_w = (const float*)d_in[3];
    const float* c_proj_b = (const float*)d_in[4];
    float* out = (float*)d_out;

    __half *xh, *wq, *wp, *qkvh, *yh;
    cudaGetSymbolAddress((void**)&xh,   g_xh);
    cudaGetSymbolAddress((void**)&wq,   g_wqkv);
    cudaGetSymbolAddress((void**)&wp,   g_wproj);
    cudaGetSymbolAddress((void**)&qkvh, g_qkvh);
    cudaGetSymbolAddress((void**)&yh,   g_yh);

    // 0) one-time fp32 -> fp16 conversions
    int n4;
    n4 = (M_ * C_) / 4;
    f2h_kernel<<<(n4 + 255) / 256, 256>>>(x, xh, n4);
    n4 = (C_ * 3 * C_) / 4;
    f2h_kernel<<<(n4 + 255) / 256, 256>>>(c_attn_w, wq, n4);
    n4 = (C_ * C_) / 4;
    f2h_kernel<<<(n4 + 255) / 256, 256>>>(c_proj_w, wp, n4);

    size_t gs = (size_t)3 * STG_B;           // 107520 B
    cudaFuncSetAttribute(gemm_h<1>, cudaFuncAttributeMaxDynamicSharedMemorySize, (int)gs);
    cudaFuncSetAttribute(gemm_h<0>, cudaFuncAttributeMaxDynamicSharedMemorySize, (int)gs);
    size_t as = (size_t)QSZ + 3 * KVSTG;     // 73728 B
    cudaFuncSetAttribute(attn_h, cudaFuncAttributeMaxDynamicSharedMemorySize, (int)as);

    // 1) QKV projection (fp16 HMMA, half out)
    gemm_h<1><<<dim3((3 * C_) / 128, M_ / 128), 256, gs>>>(xh, wq, c_attn_b, qkvh, C_, 3 * C_);

    // 2) Causal flash attention (fp16 HMMA, half out)
    attn_h<<<dim3(T_ / 128, B_ * H_), 256, as>>>(qkvh, yh);

    // 3) Output projection (fp16 HMMA, fp32 out)
    gemm_h<0><<<dim3(C_ / 128, M_ / 128), 256, gs>>>(yh, wp, c_proj_b, out, C_, C_);
}

// round 8
// speedup vs baseline: 8.8440x; 1.1159x over previous
#include <cuda_runtime.h>
#include <cuda_fp16.h>
#include <cstdint>

#define B_  2
#define T_  2048
#define C_  768
#define H_  12
#define D_  64
#define M_  (B_ * T_)      // 4096 rows

// Scratch (allocation-free), all fp16
__device__ __half g_xh[(size_t)M_ * C_];
__device__ __half g_wqkv[(size_t)C_ * 3 * C_];
__device__ __half g_wproj[(size_t)C_ * C_];
__device__ __half g_qkvh[(size_t)M_ * 3 * C_];
__device__ __half g_yh[(size_t)M_ * C_];

extern __shared__ char dynsmem[];

// ---------------------------------------------------------------------------
// PTX helpers
// ---------------------------------------------------------------------------
__device__ __forceinline__ uint32_t smem_u32(const void* p) {
    uint32_t a;
    asm("{ .reg .u64 t; cvta.to.shared.u64 t, %1; cvt.u32.u64 %0, t; }"
        : "=r"(a) : "l"(p));
    return a;
}

__device__ __forceinline__ void cpa16(uint32_t dst, const void* src) {
    asm volatile("cp.async.cg.shared.global [%0], [%1], 16;" :: "r"(dst), "l"(src));
}
#define CP_COMMIT() asm volatile("cp.async.commit_group;" ::: "memory")
#define CP_WAIT0()  asm volatile("cp.async.wait_group 0;" ::: "memory")
#define CP_WAIT1()  asm volatile("cp.async.wait_group 1;" ::: "memory")

__device__ __forceinline__ void ldsm4(unsigned* r, uint32_t a) {
    asm volatile("ldmatrix.sync.aligned.m8n8.x4.shared.b16 {%0,%1,%2,%3}, [%4];"
        : "=r"(r[0]), "=r"(r[1]), "=r"(r[2]), "=r"(r[3]) : "r"(a));
}
__device__ __forceinline__ void ldsm4t(unsigned* r, uint32_t a) {
    asm volatile("ldmatrix.sync.aligned.m8n8.x4.trans.shared.b16 {%0,%1,%2,%3}, [%4];"
        : "=r"(r[0]), "=r"(r[1]), "=r"(r[2]), "=r"(r[3]) : "r"(a));
}

__device__ __forceinline__ void mma16(float* c, const unsigned* a, const unsigned* b) {
    asm volatile(
        "mma.sync.aligned.m16n8k16.row.col.f32.f16.f16.f32 "
        "{%0,%1,%2,%3}, {%4,%5,%6,%7}, {%8,%9}, {%0,%1,%2,%3};"
        : "+f"(c[0]), "+f"(c[1]), "+f"(c[2]), "+f"(c[3])
        : "r"(a[0]), "r"(a[1]), "r"(a[2]), "r"(a[3]), "r"(b[0]), "r"(b[1]));
}

// ---------------------------------------------------------------------------
// fp32 -> fp16 conversion: one launch for all three tensors
// ---------------------------------------------------------------------------
__global__ void f2h_all(const float* __restrict__ s0, __half* __restrict__ d0, int n0,
                        const float* __restrict__ s1, __half* __restrict__ d1, int n1,
                        const float* __restrict__ s2, __half* __restrict__ d2, int n2) {
    int i = blockIdx.x * blockDim.x + threadIdx.x;
    const float* s; __half* d; int j;
    if (i < n0)               { s = s0; d = d0; j = i; }
    else if (i < n0 + n1)     { s = s1; d = d1; j = i - n0; }
    else if (i < n0 + n1 + n2){ s = s2; d = d2; j = i - n0 - n1; }
    else return;
    float4 v = reinterpret_cast<const float4*>(s)[j];
    __half2* o = reinterpret_cast<__half2*>(d) + 2 * j;
    o[0] = __floats2half2_rn(v.x, v.y);
    o[1] = __floats2half2_rn(v.z, v.w);
}

// ---------------------------------------------------------------------------
// fp16 GEMM, cp.async 3-stage pipeline + ldmatrix + m16n8k16.
// CTA tile BMT x 128, BK=64, 256 threads. fp32 accumulate.
// BMT=128: warp tile 32x64 (4x2 warps). BMT=64: warp tile 32x32 (2x4 warps).
// ---------------------------------------------------------------------------
#define SAH 72                         // A smem row stride (halves)
#define SBH 136                        // B smem row stride (halves)

template<int OUT_HALF, int BMT>
__global__ void __launch_bounds__(256, 2)
gemm_h(const __half* __restrict__ A, const __half* __restrict__ W,
       const float* __restrict__ bias, void* __restrict__ outv, int K, int N) {
    constexpr int NT   = (BMT == 128) ? 8 : 4;     // n tiles (8-wide) per warp
    constexpr int WNW  = NT * 8;                   // warp n width
    constexpr int ASZ  = BMT * SAH * 2;
    constexpr int STG  = ASZ + 64 * SBH * 2;
    constexpr int AIT  = BMT * 8 / 256;            // A fill iters

    const int tid = threadIdx.x, lane = tid & 31, warp = tid >> 5;
    const int wm = (BMT == 128) ? (warp >> 1) : (warp >> 2);
    const int wn = (BMT == 128) ? (warp & 1) : (warp & 3);
    const int g = lane >> 2, t = lane & 3;
    const int rowBase = blockIdx.y * BMT, colBase = blockIdx.x * 128;
    const uint32_t sb = smem_u32(dynsmem);

    auto fill = [&](int s, int k0) {
        uint32_t st = sb + s * STG;
        #pragma unroll
        for (int it = 0; it < AIT; it++) {               // A: BMT x 64 halves
            int e = tid + 256 * it, r = e >> 3, c = e & 7;
            cpa16(st + (r * SAH + c * 8) * 2, A + (size_t)(rowBase + r) * K + k0 + c * 8);
        }
        #pragma unroll
        for (int it = 0; it < 4; it++) {                 // B: 64 x 128 halves
            int e = tid + 256 * it, r = e >> 4, c = e & 15;
            cpa16(st + ASZ + (r * SBH + c * 8) * 2, W + (size_t)(k0 + r) * N + colBase + c * 8);
        }
    };

    float acc[2][NT][4] = {};

    const int nCh = K / 64;   // 12
    fill(0, 0);  CP_COMMIT();
    fill(1, 64); CP_COMMIT();

    for (int c = 0; c < nCh; c++) {
        if (c + 1 < nCh) CP_WAIT1(); else CP_WAIT0();
        __syncthreads();
        if (c + 2 < nCh) { fill((c + 2) % 3, (c + 2) * 64); CP_COMMIT(); }

        uint32_t st = sb + (c % 3) * STG;
        #pragma unroll
        for (int ks = 0; ks < 4; ks++) {
            unsigned af[2][4], bf[NT][2];
            #pragma unroll
            for (int mt = 0; mt < 2; mt++) {
                int row = wm * 32 + mt * 16 + (lane & 15);
                ldsm4(af[mt], st + row * (SAH * 2) + ks * 32 + ((lane & 16) ? 16 : 0));
            }
            #pragma unroll
            for (int np = 0; np < NT / 2; np++) {
                int row = ks * 16 + (lane & 15);
                int col = wn * WNW + np * 16 + ((lane & 16) ? 8 : 0);
                unsigned r4[4];
                ldsm4t(r4, st + ASZ + row * (SBH * 2) + col * 2);
                bf[2 * np][0] = r4[0]; bf[2 * np][1] = r4[1];
                bf[2 * np + 1][0] = r4[2]; bf[2 * np + 1][1] = r4[3];
            }
            #pragma unroll
            for (int mt = 0; mt < 2; mt++)
                #pragma unroll
                for (int nt = 0; nt < NT; nt++)
                    mma16(acc[mt][nt], af[mt], bf[nt]);
        }
    }

    #pragma unroll
    for (int mt = 0; mt < 2; mt++) {
        int row0 = rowBase + wm * 32 + mt * 16 + g;
        #pragma unroll
        for (int nt = 0; nt < NT; nt++) {
            int col = colBase + wn * WNW + nt * 8 + 2 * t;
            float b0 = bias[col], b1 = bias[col + 1];
            if (OUT_HALF) {
                __half* out = (__half*)outv;
                *reinterpret_cast<__half2*>(out + (size_t)row0 * N + col) =
                    __floats2half2_rn(acc[mt][nt][0] + b0, acc[mt][nt][1] + b1);
                *reinterpret_cast<__half2*>(out + (size_t)(row0 + 8) * N + col) =
                    __floats2half2_rn(acc[mt][nt][2] + b0, acc[mt][nt][3] + b1);
            } else {
                float* out = (float*)outv;
                *reinterpret_cast<float2*>(out + (size_t)row0 * N + col) =
                    make_float2(acc[mt][nt][0] + b0, acc[mt][nt][1] + b1);
                *reinterpret_cast<float2*>(out + (size_t)(row0 + 8) * N + col) =
                    make_float2(acc[mt][nt][2] + b0, acc[mt][nt][3] + b1);
            }
        }
    }
}

// ---------------------------------------------------------------------------
// fp16 causal flash attention, 64-row q-tiles (fine-grained for balance).
// 128 threads / 4 warps; warp owns a 16-row strip. exp2-domain softmax with
// scale*log2e folded into Q fragments once. cp.async 3-stage K/V pipeline.
// ---------------------------------------------------------------------------
#define SH    72                     // Q/K/V smem row stride (halves)
#define QSZ   (64 * SH * 2)          // 9216 B
#define KVSZ  (64 * SH * 2)          // 9216 B
#define KVSTG (2 * KVSZ)

__global__ void __launch_bounds__(128, 3)
attn_h(const __half* __restrict__ qkv, __half* __restrict__ y) {
    const int qb = (int)gridDim.x - 1 - (int)blockIdx.x;   // heavy tiles first
    const int bh = blockIdx.y, b = bh / H_, h = bh % H_;
    const int tid = threadIdx.x, lane = tid & 31, warp = tid >> 5;
    const int g = lane >> 2, t = lane & 3, w16 = warp * 16, q0 = qb * 64;
    const size_t rs = 3 * C_;
    const __half* base = qkv + (size_t)b * T_ * rs + h * D_;
    const uint32_t sb = smem_u32(dynsmem);
    const uint32_t sQ = sb, sKV = sb + QSZ;

    auto fillKV = [&](int s, int kb) {
        uint32_t st = sKV + s * KVSTG;
        #pragma unroll
        for (int it = 0; it < 8; it++) {
            int e = tid + 128 * it;          // 1024 segs: 512 K + 512 V
            int hv = e >> 9;
            int r = (e >> 3) & 63, c = e & 7;
            cpa16(st + hv * KVSZ + (r * SH + c * 8) * 2,
                  base + (1 + hv) * C_ + (size_t)(kb * 64 + r) * rs + c * 8);
        }
    };

    // Prologue: Q + KV(0) in group 0, KV(1) in group 1.
    #pragma unroll
    for (int it = 0; it < 4; it++) {
        int e = tid + 128 * it, r = e >> 3, c = e & 7;
        cpa16(sQ + (r * SH + c * 8) * 2, base + (size_t)(q0 + r) * rs + c * 8);
    }
    const int nkb = qb + 1;
    fillKV(0, 0); CP_COMMIT();
    if (nkb > 1) { fillKV(1, 1); CP_COMMIT(); }

    if (nkb > 1) CP_WAIT1(); else CP_WAIT0();
    __syncthreads();

    // Q fragments, loaded once; fold (1/8)*log2(e) scale into them.
    const __half2 qscale = __float2half2_rn(0.18033688f);   // 0.125 * log2(e)
    unsigned qf[4][4];
    #pragma unroll
    for (int ks = 0; ks < 4; ks++) {
        int row = w16 + (lane & 15);
        ldsm4(qf[ks], sQ + row * (SH * 2) + ks * 32 + ((lane & 16) ? 16 : 0));
        #pragma unroll
        for (int j = 0; j < 4; j++) {
            __half2 v = *reinterpret_cast<__half2*>(&qf[ks][j]);
            v = __hmul2(v, qscale);
            qf[ks][j] = *reinterpret_cast<unsigned*>(&v);
        }
    }

    float oAcc[8][4] = {};
    float m_i[2] = {-1e30f, -1e30f}, l_i[2] = {0.0f, 0.0f};

    for (int kb = 0; kb < nkb; kb++) {
        if (kb + 1 < nkb) CP_WAIT1(); else CP_WAIT0();
        __syncthreads();
        if (kb + 2 < nkb) { fillKV((kb + 2) % 3, kb + 2); CP_COMMIT(); }

        const uint32_t sK = sKV + (kb % 3) * KVSTG;
        const uint32_t sV = sK + KVSZ;

        // ---- S = Q @ K^T  (log2 domain) ----
        float sA[8][4] = {};
        #pragma unroll
        for (int ks = 0; ks < 4; ks++) {
            unsigned bf[8][2];
            #pragma unroll
            for (int np = 0; np < 4; np++) {
                int row = np * 16 + ((lane & 16) ? 8 : 0) + (lane & 7);
                unsigned r4[4];
                ldsm4(r4, sK + row * (SH * 2) + ks * 32 + ((lane & 8) ? 16 : 0));
                bf[2 * np][0] = r4[0]; bf[2 * np][1] = r4[1];
                bf[2 * np + 1][0] = r4[2]; bf[2 * np + 1][1] = r4[3];
            }
            #pragma unroll
            for (int nt = 0; nt < 8; nt++)
                mma16(sA[nt], qf[ks], bf[nt]);
        }

        // causal mask (near-diagonal blocks only)
        if (kb * 64 + 63 > q0 + w16) {
            int qr0 = q0 + w16 + g, qr1 = qr0 + 8;
            #pragma unroll
            for (int nt = 0; nt < 8; nt++) {
                int kc = kb * 64 + nt * 8 + 2 * t;
                if (kc     > qr0) sA[nt][0] = -1e30f;
                if (kc + 1 > qr0) sA[nt][1] = -1e30f;
                if (kc     > qr1) sA[nt][2] = -1e30f;
                if (kc + 1 > qr1) sA[nt][3] = -1e30f;
            }
        }

        // ---- online softmax (exp2 domain; rows g, g+8; quad reduce) ----
        float mx0 = -1e30f, mx1 = -1e30f;
        #pragma unroll
        for (int nt = 0; nt < 8; nt++) {
            mx0 = fmaxf(mx0, fmaxf(sA[nt][0], sA[nt][1]));
            mx1 = fmaxf(mx1, fmaxf(sA[nt][2], sA[nt][3]));
        }
        #pragma unroll
        for (int off = 1; off <= 2; off <<= 1) {
            mx0 = fmaxf(mx0, __shfl_xor_sync(0xffffffffu, mx0, off));
            mx1 = fmaxf(mx1, __shfl_xor_sync(0xffffffffu, mx1, off));
        }
        float mn0 = fmaxf(m_i[0], mx0), mn1 = fmaxf(m_i[1], mx1);
        float al0 = exp2f(m_i[0] - mn0), al1 = exp2f(m_i[1] - mn1);

        unsigned pf[4][4];
        float ps0 = 0.0f, ps1 = 0.0f;
        #pragma unroll
        for (int nt = 0; nt < 8; nt++) {
            float p0 = exp2f(sA[nt][0] - mn0), p1 = exp2f(sA[nt][1] - mn0);
            float p2 = exp2f(sA[nt][2] - mn1), p3 = exp2f(sA[nt][3] - mn1);
            ps0 += p0 + p1; ps1 += p2 + p3;
            __half2 hA = __floats2half2_rn(p0, p1);
            __half2 hB = __floats2half2_rn(p2, p3);
            pf[nt >> 1][(nt & 1) * 2 + 0] = *reinterpret_cast<unsigned*>(&hA);
            pf[nt >> 1][(nt & 1) * 2 + 1] = *reinterpret_cast<unsigned*>(&hB);
        }
        #pragma unroll
        for (int off = 1; off <= 2; off <<= 1) {
            ps0 += __shfl_xor_sync(0xffffffffu, ps0, off);
            ps1 += __shfl_xor_sync(0xffffffffu, ps1, off);
        }
        l_i[0] = l_i[0] * al0 + ps0;
        l_i[1] = l_i[1] * al1 + ps1;
        m_i[0] = mn0; m_i[1] = mn1;
        #pragma unroll
        for (int nt = 0; nt < 8; nt++) {
            oAcc[nt][0] *= al0; oAcc[nt][1] *= al0;
            oAcc[nt][2] *= al1; oAcc[nt][3] *= al1;
        }

        // ---- O += P @ V ----
        #pragma unroll
        for (int kt = 0; kt < 4; kt++) {
            unsigned vf[8][2];
            #pragma unroll
            for (int np = 0; np < 4; np++) {
                int row = kt * 16 + (lane & 15);
                unsigned r4[4];
                ldsm4t(r4, sV + row * (SH * 2) + np * 32 + ((lane & 16) ? 16 : 0));
                vf[2 * np][0] = r4[0]; vf[2 * np][1] = r4[1];
                vf[2 * np + 1][0] = r4[2]; vf[2 * np + 1][1] = r4[3];
            }
            #pragma unroll
            for (int nt = 0; nt < 8; nt++)
                mma16(oAcc[nt], pf[kt], vf[nt]);
        }
    }

    // ---- epilogue: normalize, store y (half) ----
    float inv0 = 1.0f / l_i[0], inv1 = 1.0f / l_i[1];
    int qr = q0 + w16 + g;
    __half* yo = y + ((size_t)b * T_ + qr) * C_ + h * D_;
    #pragma unroll
    for (int nt = 0; nt < 8; nt++) {
        int col = nt * 8 + 2 * t;
        *reinterpret_cast<__half2*>(yo + col) =
            __floats2half2_rn(oAcc[nt][0] * inv0, oAcc[nt][1] * inv0);
        *reinterpret_cast<__half2*>(yo + (size_t)8 * C_ + col) =
            __floats2half2_rn(oAcc[nt][2] * inv1, oAcc[nt][3] * inv1);
    }
}

// ---------------------------------------------------------------------------
extern "C" void kernel_launch(void* const* d_in, const int* in_sizes, int n_in,
                              void* d_out, int out_size) {
    const float* x        = (const float*)d_in[0];
    const float* c_attn_w = (const float*)d_in[1];
    const float* c_attn_b = (const float*)d_in[2];
    const float* c_proj_w = (const float*)d_in[3];
    const float* c_proj_b = (const float*)d_in[4];
    float* out = (float*)d_out;

    __half *xh, *wq, *wp, *qkvh, *yh;
    cudaGetSymbolAddress((void**)&xh,   g_xh);
    cudaGetSymbolAddress((void**)&wq,   g_wqkv);
    cudaGetSymbolAddress((void**)&wp,   g_wproj);
    cudaGetSymbolAddress((void**)&qkvh, g_qkvh);
    cudaGetSymbolAddress((void**)&yh,   g_yh);

    // 0) one-time fp32 -> fp16 conversions (single launch)
    int n0 = (M_ * C_) / 4, n1 = (C_ * 3 * C_) / 4, n2 = (C_ * C_) / 4;
    f2h_all<<<(n0 + n1 + n2 + 255) / 256, 256>>>(x, xh, n0, c_attn_w, wq, n1, c_proj_w, wp, n2);

    size_t gs128 = (size_t)3 * (128 * SAH * 2 + 64 * SBH * 2);   // 107520 B
    size_t gs64  = (size_t)3 * (64 * SAH * 2 + 64 * SBH * 2);    //  79872 B
    cudaFuncSetAttribute(gemm_h<1, 128>, cudaFuncAttributeMaxDynamicSharedMemorySize, (int)gs128);
    cudaFuncSetAttribute(gemm_h<0, 64>,  cudaFuncAttributeMaxDynamicSharedMemorySize, (int)gs64);
    size_t as = (size_t)QSZ + 3 * KVSTG;                          // 64512 B
    cudaFuncSetAttribute(attn_h, cudaFuncAttributeMaxDynamicSharedMemorySize, (int)as);

    // 1) QKV projection (fp16 HMMA, half out): tile 128x128, grid (18,32)
    gemm_h<1, 128><<<dim3((3 * C_) / 128, M_ / 128), 256, gs128>>>(xh, wq, c_attn_b, qkvh, C_, 3 * C_);

    // 2) Causal flash attention: 64-row q-tiles, grid (32,24)
    attn_h<<<dim3(T_ / 64, B_ * H_), 128, as>>>(qkvh, yh);

    // 3) Output projection (fp16 HMMA, fp32 out): tile 64x128, grid (6,64)
    gemm_h<0, 64><<<dim3(C_ / 128, M_ / 64), 256, gs64>>>(yh, wp, c_proj_b, out, C_, C_);
}